// round 14
// baseline (speedup 1.0000x reference)
#include <cuda_runtime.h>
#include <cuda_bf16.h>

#define NPSI 256
#define MM 8
#define KK 4

typedef unsigned long long u64c;   // carrier for packed f32x2

__device__ __forceinline__ u64c f2pk(float lo, float hi) {
    u64c r;
    asm("mov.b64 %0, {%1, %2};"
        : "=l"(r) : "r"(__float_as_uint(lo)), "r"(__float_as_uint(hi)));
    return r;
}
__device__ __forceinline__ void f2unpk(u64c v, float& lo, float& hi) {
    unsigned int a, b;
    asm("mov.b64 {%0, %1}, %2;" : "=r"(a), "=r"(b) : "l"(v));
    lo = __uint_as_float(a);
    hi = __uint_as_float(b);
}
__device__ __forceinline__ u64c f2fma(u64c a, u64c b, u64c c) {
    u64c d;
    asm("fma.rn.f32x2 %0, %1, %2, %3;" : "=l"(d) : "l"(a), "l"(b), "l"(c));
    return d;
}
__device__ __forceinline__ u64c f2add(u64c a, u64c b) {
    u64c d;
    asm("add.rn.f32x2 %0, %1, %2;" : "=l"(d) : "l"(a), "l"(b));
    return d;
}
// raw EX2 (what __expf bottoms out in, minus its extra log2e multiply)
__device__ __forceinline__ float fex2(float a) {
    float r;
    asm("ex2.approx.f32 %0, %1;" : "=f"(r) : "f"(a));
    return r;
}

// K = sqrt(log2(e)/2):  exp(-0.5*y^2) == 2^(-(K*y)^2)
#define KEXP 0.84932184f

__global__ __launch_bounds__(256)
void eikonal_field_kernel(const float* __restrict__ t_ptr,
                          const float* __restrict__ psi,
                          const float* __restrict__ theta,
                          const float* __restrict__ varphi,
                          const float* __restrict__ q_vals,
                          const float* __restrict__ theta0,
                          const float* __restrict__ omega,
                          const float* __restrict__ psi0,
                          const float* __restrict__ psi_scale,
                          const float* __restrict__ alpha_scale,
                          const float* __restrict__ gh,
                          const int*   __restrict__ n_arr,
                          float* __restrict__ out,
                          int N)
{
    __shared__ float sq[NPSI];
    __shared__ float sm[NPSI];                 // FD slopes (jnp.gradient), prebuilt
    __shared__ float s_th0[MM], s_p0[MM], s_ips[MM], s_ias[MM], s_nf[MM];
    __shared__ float s_ipsK[MM], s_iasK[MM];   // K/psi_scale, K/alpha_scale
    __shared__ float s_omt[MM], s_nfc[MM];     // omega*t/2pi (uniform t!), n/2pi
    // Packed Gauss-Hermite coefficient table, folded at load time:
    //   A(x) = Q0 + c1*x + Q3*x^2,  Q0 = c0 - 2*c3 - 2*c5,  Q3 = 4*c3
    //   B(x) = c2 + c4*x
    //   C    = 4*c5
    // Layout per m (12 u64): [Q0_01, c1_01, Q3_01, c2_01, c4_01, C_01,
    //                         Q0_23, c1_23, Q3_23, c2_23, c4_23, C_23]
    __shared__ u64c spk[MM * 12];

    const float INV_2PI_H = 0.159154943091895335769f;

    const int tid = threadIdx.x;
    for (int j = tid; j < NPSI; j += blockDim.x) {
        sq[j] = q_vals[j];
        // slopes read GLOBAL q_vals directly (no dependence on sq -> one sync)
        sm[j] = (j == 0)        ? (q_vals[1] - q_vals[0])
              : (j == NPSI - 1) ? (q_vals[NPSI - 1] - q_vals[NPSI - 2])
                                : 0.5f * (q_vals[j + 1] - q_vals[j - 1]);
    }
    if (tid < MM) {
        s_th0[tid]  = theta0[tid];
        s_p0[tid]   = psi0[tid];
        const float ips = 1.0f / psi_scale[tid];
        const float ias = 1.0f / alpha_scale[tid];
        s_ips[tid]  = ips;
        s_ias[tid]  = ias;
        s_ipsK[tid] = ips * KEXP;
        s_iasK[tid] = ias * KEXP;
        const float nf = (float)n_arr[tid];
        s_nf[tid]   = nf;
        s_nfc[tid]  = nf * INV_2PI_H;
        // t is a uniform scalar input: fold omega*t/2pi once per block.
        s_omt[tid]  = omega[tid] * INV_2PI_H * t_ptr[0];
    }
    if (tid < MM * 12) {
        const int m    = tid / 12;
        const int r    = tid % 12;
        const int pair = r / 6;             // 0 -> comps (0,1), 1 -> comps (2,3)
        const int cs   = r % 6;             // which coefficient set
        const int cc0  = pair * 2;
        const float* c = gh + m * 24;
        const float* a = c + cc0 * 6;       // comp lo
        const float* b = c + (cc0 + 1) * 6; // comp hi
        float lo, hi;
        switch (cs) {
            case 0: lo = a[0] - 2.f * a[3] - 2.f * a[5];
                    hi = b[0] - 2.f * b[3] - 2.f * b[5]; break;   // Q0
            case 1: lo = a[1];        hi = b[1];        break;    // c1
            case 2: lo = 4.f * a[3];  hi = 4.f * b[3];  break;    // Q3
            case 3: lo = a[2];        hi = b[2];        break;    // c2
            case 4: lo = a[4];        hi = b[4];        break;    // c4
            default: lo = 4.f * a[5]; hi = 4.f * b[5];  break;    // C
        }
        spk[tid] = f2pk(lo, hi);
    }
    __syncthreads();

    const int i = blockIdx.x * blockDim.x + tid;
    if (i >= N) return;

    const float ps = psi[i];
    const float th = theta[i];
    const float vp = varphi[i];

    // ---- cubic Hermite interp of q_vals at psi (uniform grid, FD slopes) ----
    float u = ps * 255.0f;                 // (psi - X0)/H, H = 1/255
    int j = (int)floorf(u);
    j = min(max(j, 0), NPSI - 2);
    const float s  = u - (float)j;
    const float s2 = s * s;
    const float s3 = s2 * s;
    const float w0 =  2.f * s3 - 3.f * s2 + 1.f;
    const float w1 =        s3 - 2.f * s2 + s;
    const float w2 = -2.f * s3 + 3.f * s2;
    const float w3 =        s3 -       s2;

    // branch-free: slopes come from the prebuilt shared table
    const float q = w0 * sq[j] + w1 * sm[j] + w2 * sq[j + 1] + w3 * sm[j + 1];

    // aoff cancels exactly: alpha0 = q*theta0 + aoff by linearity of the
    // interp, so y*alpha_scale = q*(theta + 2*pi*k - theta0) and the phase
    // never sees aoff either.

    const float TWO_PI = 6.283185307179586476925f;
    const float q2pi   = q * TWO_PI;

    // Packed accumulators: lane0 sums (+cos) terms, lane1 sums (+sin) terms;
    // the subtraction phi = lo - hi happens once at the end.
    u64c acc01 = 0ull;   // (sum p0*g*cp, sum p1*g*sp)
    u64c acc23 = 0ull;   // (sum p2*g*cp, sum p3*g*sp)

    #pragma unroll
    for (int m = 0; m < MM; ++m) {
        const float dps = ps - s_p0[m];
        const float x   = dps * s_ips[m];
        const float xw  = dps * s_ipsK[m];
        const float gx  = fex2(-xw * xw);     // exp(-0.5*x^2)

        const u64c xx  = f2pk(x, x);
        const u64c x22 = f2pk(x * x, x * x);
        const u64c* pm = &spk[m * 12];
        const u64c A01 = f2fma(pm[2], x22, f2fma(pm[1], xx, pm[0]));
        const u64c B01 = f2fma(pm[4], xx, pm[3]);
        const u64c C01 = pm[5];
        const u64c A23 = f2fma(pm[8], x22, f2fma(pm[7], xx, pm[6]));
        const u64c B23 = f2fma(pm[10], xx, pm[9]);
        const u64c C23 = pm[11];

        const float qdth = q * (th - s_th0[m]);
        const float y0   = qdth * s_ias[m];          // y at k=0
        const float dy   = q2pi * s_ias[m];          // y step per k
        u64c  yy   = f2pk(y0, y0);                   // packed (y, y)
        const u64c dypk = f2pk(dy, dy);
        float       w    = qdth * s_iasK[m];         // K*y, tracked for exp
        const float dw   = q2pi * s_iasK[m];

        // phase in CYCLES: pr = (omega*t - n*vp + n*qdth)/2pi. omega*t/2pi is
        // uniform and precomputed per block; two FFMAs total. The phase
        // already carries ~2e-5 rad of fp32 rounding (in the reference too),
        // so this costs no net accuracy.
        const float nfc = s_nfc[m];
        float pr = fmaf(nfc, qdth, fmaf(-nfc, vp, s_omt[m]));
        pr -= rintf(pr);
        float cp, sp;
        __sincosf(TWO_PI * pr, &sp, &cp);

        const float r  = s_nf[m] * q;
        const float rr = r - rintf(r);               // reduce delta to [-pi, pi]
        float cd, sd;
        __sincosf(TWO_PI * rr, &sd, &cd);

        // Fold the constant per-m Gaussian factor gx into the phasor (the
        // rotation recurrence is linear in (u, v)).
        float uph = gx * cp;
        float vph = gx * sp;

        #pragma unroll
        for (int k = 0; k < KK; ++k) {
            const float e = fex2(-w * w);   // exp(-0.5*y^2); no recurrence —
            // dy can be ~100, so e underflows/recovers non-monotonically and a
            // multiplicative recurrence would be wrong after an underflow.
            const u64c gcs = f2pk(e * uph, e * vph);
            // Horner: p = (C*y + B)*y + A  — yy stays packed across iterations.
            const u64c p01 = f2fma(f2fma(C01, yy, B01), yy, A01);
            const u64c p23 = f2fma(f2fma(C23, yy, B23), yy, A23);
            acc01 = f2fma(p01, gcs, acc01);
            acc23 = f2fma(p23, gcs, acc23);
            if (k < KK - 1) {
                const float un = fmaf(uph, cd, -(vph * sd));  // rotate by delta
                vph = fmaf(vph, cd, uph * sd);
                uph = un;
                yy = f2add(yy, dypk);
                w += dw;
            }
        }
    }

    float a0, a1, a2, a3;
    f2unpk(acc01, a0, a1);
    f2unpk(acc23, a2, a3);
    out[i]     = a0 - a1;   // phi
    out[N + i] = a2 - a3;   // apar
}

extern "C" void kernel_launch(void* const* d_in, const int* in_sizes, int n_in,
                              void* d_out, int out_size)
{
    // metadata order: t, psi, theta, varphi, q_vals, aoff_vals, theta0, omega,
    //                 psi0, psi_scale, alpha_scale, gh_coefs, n
    const float* t           = (const float*)d_in[0];
    const float* psi         = (const float*)d_in[1];
    const float* theta       = (const float*)d_in[2];
    const float* varphi      = (const float*)d_in[3];
    const float* q_vals      = (const float*)d_in[4];
    // d_in[5] = aoff_vals: provably cancels out of both outputs
    const float* theta0      = (const float*)d_in[6];
    const float* omega       = (const float*)d_in[7];
    const float* psi0        = (const float*)d_in[8];
    const float* psi_scale   = (const float*)d_in[9];
    const float* alpha_scale = (const float*)d_in[10];
    const float* gh_coefs    = (const float*)d_in[11];
    const int*   n_arr       = (const int*)d_in[12];

    const int N = in_sizes[1];
    const int threads = 256;
    const int blocks = (N + threads - 1) / threads;
    eikonal_field_kernel<<<blocks, threads>>>(t, psi, theta, varphi, q_vals,
                                              theta0, omega, psi0, psi_scale,
                                              alpha_scale, gh_coefs, n_arr,
                                              (float*)d_out, N);
}